// round 7
// baseline (speedup 1.0000x reference)
#include <cuda_runtime.h>
#include <cstdint>

// x[32,64,112,112] (*) w[128,64,3,3] + b[128] -> out[32,128,112,112], pad=1
// Conv as 9 shifted GEMMs. CTA = (n, 2 output rows): D[128 oc][224 px].
// Raw input tile [4 rows][114 cols][32 ic] staged per ic-half; B fragments via
// shifted ldmatrix directly from the raw tile (no im2col). 512 thr, 1 CTA/SM.

#define KTOT 576
#define STR  36                          // smem row stride (words)
#define RAW_WORDS  (4*114*STR)           // 16416
#define ABUF_WORDS (128*STR)             // 4608
#define SMEM_BYTES ((RAW_WORDS + 2*ABUF_WORDS)*4)   // 102528

__device__ uint32_t Wt[2*9*128*32];      // [half][pass][oc][icl], tf32

__device__ __forceinline__ uint32_t tf32c(float f) {
    uint32_t u; asm("cvt.rna.tf32.f32 %0, %1;" : "=r"(u) : "f"(f)); return u;
}
__device__ __forceinline__ void ldsm4(uint32_t* r, uint32_t addr) {
    asm volatile("ldmatrix.sync.aligned.m8n8.x4.shared.b16 {%0,%1,%2,%3}, [%4];"
                 : "=r"(r[0]), "=r"(r[1]), "=r"(r[2]), "=r"(r[3]) : "r"(addr));
}
__device__ __forceinline__ void ldsm2(uint32_t* r, uint32_t addr) {
    asm volatile("ldmatrix.sync.aligned.m8n8.x2.shared.b16 {%0,%1}, [%2];"
                 : "=r"(r[0]), "=r"(r[1]) : "r"(addr));
}
__device__ __forceinline__ void mma8(float* d, const uint32_t* a, uint32_t b0, uint32_t b1) {
    asm volatile(
        "mma.sync.aligned.m16n8k8.row.col.f32.tf32.tf32.f32 "
        "{%0,%1,%2,%3}, {%4,%5,%6,%7}, {%8,%9}, {%0,%1,%2,%3};"
        : "+f"(d[0]), "+f"(d[1]), "+f"(d[2]), "+f"(d[3])
        : "r"(a[0]), "r"(a[1]), "r"(a[2]), "r"(a[3]), "r"(b0), "r"(b1));
}

__global__ void prep_weights(const float* __restrict__ w) {
    const int i = blockIdx.x * 256 + threadIdx.x;     // 73728 total
    const int icl = i & 31;
    const int t   = i >> 5;
    const int oc  = t & 127;
    const int hr  = t >> 7;             // h*9 + r
    const int r   = hr % 9;
    const int h   = hr / 9;
    Wt[i] = tf32c(w[oc * KTOT + (h * 32 + icl) * 9 + r]);
}

__global__ __launch_bounds__(512, 1)
void conv3x3_shift2(const float* __restrict__ x,
                    const float* __restrict__ bias,
                    float* __restrict__ out)
{
    extern __shared__ uint32_t sm[];
    uint32_t* const Raw = sm;                    // [4*114 px][36]
    uint32_t* const Asm = sm + RAW_WORDS;        // 2 x [128 oc][36]

    const int tid = threadIdx.x;
    const int lid = tid & 31;
    const int wid = tid >> 5;                    // 0..15
    const int wm  = wid & 3;                     // M-group: 32 oc
    const int wr  = (wid >> 2) & 1;              // output row within CTA
    const int wc  = wid >> 3;                    // col half: 56 px

    const int bz  = blockIdx.x;                  // 32*56
    const int n   = bz / 56;
    const int oh0 = (bz - n * 56) * 2;

    const uint32_t smem_b = (uint32_t)__cvta_generic_to_shared(sm);
    const uint32_t aOff  = smem_b + RAW_WORDS * 4 +
                           4 * ((wm * 32 + (lid & 15)) * STR + ((lid >> 4) << 2));
    const uint32_t bOff4 = 4 * ((lid & 15) * STR + ((lid >> 4) << 2));
    const uint32_t bOff2 = 4 * ((lid & 7) * STR + (((lid >> 3) & 1) << 2));

    float acc[2][7][4];
    #pragma unroll
    for (int mt = 0; mt < 2; ++mt)
        #pragma unroll
        for (int nt = 0; nt < 7; ++nt)
            #pragma unroll
            for (int e = 0; e < 4; ++e) acc[mt][nt][e] = 0.0f;

    // ---- stage A pass tile from pre-transposed weights (fully coalesced) ----
    auto stage_A = [&](int h, int r, int buf) {
        const uint32_t* src = Wt + (h * 9 + r) * 4096;          // [128][32]
        uint32_t* dst = Asm + buf * ABUF_WORDS;
        const int q = tid & 7, ocr = tid >> 3;                  // ocr 0..63
        #pragma unroll
        for (int it = 0; it < 2; ++it) {
            const int oc = it * 64 + ocr;
            const uint4 v = *reinterpret_cast<const uint4*>(src + oc * 32 + q * 4);
            *reinterpret_cast<uint4*>(dst + oc * STR + q * 4) = v;
        }
    };

    // ---- stage raw input tile for ic-half h: [4 rows][114 cols][32 ic] ----
    auto stage_raw = [&](int h) {
        const float* xb = x + ((size_t)(n * 64 + h * 32) * 112) * 112;
        for (int idx = tid; idx < 4 * 8 * 114; idx += 512) {
            const int combo = idx / 114;
            const int col   = idx - combo * 114;
            const int row   = combo >> 3;                 // 0..3
            const int icq   = combo & 7;
            const int ih = oh0 - 1 + row;
            const int iw = col - 1;
            uint4 t;
            if (ih >= 0 && ih < 112 && iw >= 0 && iw < 112) {
                const float* p = xb + (size_t)icq * 4 * 12544 + ih * 112 + iw;
                t.x = tf32c(p[0]);
                t.y = tf32c(p[12544]);
                t.z = tf32c(p[25088]);
                t.w = tf32c(p[37632]);
            } else {
                t.x = t.y = t.z = t.w = 0u;
            }
            *reinterpret_cast<uint4*>(Raw + (row * 114 + col) * STR + icq * 4) = t;
        }
    };

    // ---- one (kh,kw) GEMM pass, K=32 ----
    auto compute = [&](int r, int buf) {
        const int kh = r / 3, kw = r - 3 * kh;
        const int prow = kh + wr;                         // raw row for this warp
        const uint32_t b4 = smem_b + 4 * ((prow * 114 + kw + wc * 56) * STR) + bOff4;
        const uint32_t b2 = smem_b + 4 * ((prow * 114 + kw + wc * 56 + 48) * STR) + bOff2;
        const uint32_t aB = aOff + buf * (ABUF_WORDS * 4);
        #pragma unroll
        for (int s = 0; s < 4; ++s) {
            uint32_t a0[4], a1[4];
            ldsm4(a0, aB + s * 32);
            ldsm4(a1, aB + 16 * STR * 4 + s * 32);
            #pragma unroll
            for (int np = 0; np < 3; ++np) {
                uint32_t bf[4];
                ldsm4(bf, b4 + np * (16 * STR * 4) + s * 32);
                #pragma unroll
                for (int half = 0; half < 2; ++half) {
                    const int nt = np * 2 + half;
                    mma8(acc[0][nt], a0, bf[half], bf[2 + half]);
                    mma8(acc[1][nt], a1, bf[half], bf[2 + half]);
                }
            }
            uint32_t bg[2];
            ldsm2(bg, b2 + s * 32);
            mma8(acc[0][6], a0, bg[0], bg[1]);
            mma8(acc[1][6], a1, bg[0], bg[1]);
        }
    };

    for (int h = 0; h < 2; ++h) {
        stage_raw(h);
        stage_A(h, 0, 0);
        __syncthreads();
        #pragma unroll 1
        for (int r = 0; r < 9; ++r) {
            if (r < 8) stage_A(h, r + 1, (r + 1) & 1);    // overlap next A stage
            compute(r, r & 1);
            __syncthreads();
        }
    }

    // ---- epilogue ----
    const int g = lid >> 2, q = lid & 3;
    const int oh = oh0 + wr;
    #pragma unroll
    for (int mt = 0; mt < 2; ++mt) {
        const int oc0 = wm * 32 + mt * 16 + g;
        const float bv0 = bias[oc0];
        const float bv1 = bias[oc0 + 8];
        #pragma unroll
        for (int nt = 0; nt < 7; ++nt) {
            const int col = wc * 56 + nt * 8 + 2 * q;
            float2 v0, v1;
            v0.x = acc[mt][nt][0] + bv0; v0.y = acc[mt][nt][1] + bv0;
            v1.x = acc[mt][nt][2] + bv1; v1.y = acc[mt][nt][3] + bv1;
            float* base = out + (((size_t)n * 128 + oc0) * 112 + oh) * 112 + col;
            *reinterpret_cast<float2*>(base) = v0;
            *reinterpret_cast<float2*>(base + 8 * 112 * 112) = v1;
        }
    }
}

extern "C" void kernel_launch(void* const* d_in, const int* in_sizes, int n_in,
                              void* d_out, int out_size)
{
    const float* x    = (const float*)d_in[0];
    const float* wgt  = (const float*)d_in[1];
    const float* bias = (const float*)d_in[2];
    float* out        = (float*)d_out;

    prep_weights<<<288, 256>>>(wgt);   // one-time weight re-layout + tf32

    cudaFuncSetAttribute(conv3x3_shift2,
                         cudaFuncAttributeMaxDynamicSharedMemorySize, SMEM_BYTES);
    conv3x3_shift2<<<32 * 56, 512, SMEM_BYTES>>>(x, bias, out);
}